// round 7
// baseline (speedup 1.0000x reference)
#include <cuda_runtime.h>
#include <cuda_fp16.h>
#include <cstdint>

#define DEVINL __device__ __forceinline__

DEVINL uint32_t smem_u32(const void* p) {
    uint32_t a;
    asm("{ .reg .u64 t; cvta.to.shared.u64 t, %1; cvt.u32.u64 %0, t; }"
        : "=r"(a) : "l"(p));
    return a;
}

// Swizzles: SWZ for 128B-row tiles, SWZ64 for 64B-row tiles (both keep
// ldmatrix.x4's 8-address phases on distinct 16B bank slots)
#define SWZ(o)   ((o) ^ (((o) >> 3) & 0x70))
#define SWZ64(o) ((o) ^ (((o) >> 3) & 0x30))

DEVINL void ldsm_x4(uint32_t& r0, uint32_t& r1, uint32_t& r2, uint32_t& r3, uint32_t addr) {
    asm volatile("ldmatrix.sync.aligned.m8n8.x4.shared.b16 {%0,%1,%2,%3}, [%4];"
                 : "=r"(r0), "=r"(r1), "=r"(r2), "=r"(r3) : "r"(addr));
}

DEVINL void mma_16816(float* c, uint32_t a0, uint32_t a1, uint32_t a2, uint32_t a3,
                      uint32_t b0, uint32_t b1) {
    asm volatile(
        "mma.sync.aligned.m16n8k16.row.col.f32.f16.f16.f32 "
        "{%0,%1,%2,%3}, {%4,%5,%6,%7}, {%8,%9}, {%0,%1,%2,%3};"
        : "+f"(c[0]), "+f"(c[1]), "+f"(c[2]), "+f"(c[3])
        : "r"(a0), "r"(a1), "r"(a2), "r"(a3), "r"(b0), "r"(b1));
}

DEVINL void cp_async16(uint32_t smem_addr, const void* gptr) {
    asm volatile("cp.async.cg.shared.global [%0], [%1], 16;"
                 :: "r"(smem_addr), "l"(gptr));
}
#define CP_COMMIT() asm volatile("cp.async.commit_group;" ::: "memory")
#define CP_WAIT(n)  asm volatile("cp.async.wait_group %0;" :: "n"(n) : "memory")

// ============================================================================
// Problem constants
// ============================================================================
static constexpr int N_ROWS  = 262144;
static constexpr int M_TILE  = 128;
static constexpr int N_CTAS  = N_ROWS / M_TILE;  // 2048
static constexpr int THREADS = 512;              // 16 warps, 4m x 4n warp grid

// fp16 transposed weights (scratch via device globals)
__device__ __align__(16) __half w1h_g[512 * 1024];  // [N=512][K=1024]
__device__ __align__(16) __half w2h_g[256 * 512];   // [N=256][K=512]

// ---------------- SMEM layout (bytes) — 232448 = 227KB exactly --------------
static constexpr int SM_W0    = 0;       // 2048 f32 ([2][1024])  = 8192
static constexpr int SM_B0    = 8192;    // 1024 f32              = 4096
static constexpr int SM_B1    = 12288;   // 512 f32               = 2048
static constexpr int SM_B2    = 14336;   // 256 f32               = 1024
static constexpr int SM_W3    = 15360;   // 768 f32               = 3072  -> 18432
static constexpr int SM_H2    = 19456;   // 8 blocks x 16KB (SWZ128) -> 150528
static constexpr int SM_A1    = 150528;  // 2 x 8KB A chunk (128x32 fp16, SWZ64) -> 166912
static constexpr int SM_PART  = 150528;  // overlay on A1 (dead at layer 3)
static constexpr int SM_BR    = 166912;  // 4 x 16KB B stages (256x32 fp16, SWZ64) -> 232448
static constexpr int SMEM_TOTAL = 232448;

static constexpr int N_CHUNKS = 80;  // 32 (pass0) + 32 (pass1) + 16 (layer2)

// ============================================================================
// Prep: transpose + fp16-convert W1, W2
// ============================================================================
__global__ void prep_weights(const float* __restrict__ W1, const float* __restrict__ W2) {
    int i = blockIdx.x * blockDim.x + threadIdx.x;
    if (i < 512 * 1024) {
        int n = i >> 10, k = i & 1023;
        w1h_g[i] = __float2half_rn(W1[k * 512 + n]);
    } else {
        int j = i - 512 * 1024;
        if (j < 256 * 512) {
            int n = j >> 9, k = j & 511;
            w2h_g[j] = __float2half_rn(W2[k * 256 + n]);
        }
    }
}

// gmem source for global chunk index c (task = row rb, 16B segment sg of 4)
DEVINL const __half* chunk_src(int c, int rb, int sg) {
    if (c < 64) {
        const int row = ((c & 32) ? 256 : 0) + rb;
        return w1h_g + row * 1024 + (c & 31) * 32 + sg * 8;
    }
    return w2h_g + rb * 512 + (c - 64) * 32 + sg * 8;
}

// ============================================================================
// Fused MLP kernel
// ============================================================================
__global__ __launch_bounds__(THREADS, 1) void fused_mlp_kernel(
    const float* __restrict__ coord,
    const float* __restrict__ W0, const float* __restrict__ b0,
    const float* __restrict__ b1, const float* __restrict__ b2,
    const float* __restrict__ W3, const float* __restrict__ b3,
    float* __restrict__ out)
{
    extern __shared__ char smem[];
    const uint32_t sb = smem_u32(smem);
    const int tid  = threadIdx.x;
    const int wid  = tid >> 5;
    const int lane = tid & 31;
    const int row0 = blockIdx.x * M_TILE;

    float* sW0 = (float*)(smem + SM_W0);
    float* sB0 = (float*)(smem + SM_B0);
    float* sB1 = (float*)(smem + SM_B1);
    float* sB2 = (float*)(smem + SM_B2);
    float* sW3 = (float*)(smem + SM_W3);
    float* sPart = (float*)(smem + SM_PART);

    // ---- kick off B pipeline for chunks 0..2 immediately ----
    const int rb0 = tid >> 2;        // 0..127
    const int sg  = tid & 3;
    #pragma unroll
    for (int c = 0; c < 3; ++c) {
        const uint32_t dst = sb + SM_BR + c * 16384;
        cp_async16(dst + SWZ64((uint32_t)(rb0 * 64 + sg * 16)), chunk_src(c, rb0, sg));
        cp_async16(dst + SWZ64((uint32_t)((rb0 + 128) * 64 + sg * 16)), chunk_src(c, rb0 + 128, sg));
        CP_COMMIT();
    }

    // ---- preload constants ----
    for (int i = tid; i < 2048; i += THREADS) sW0[i] = W0[i];
    for (int i = tid; i < 1024; i += THREADS) sB0[i] = b0[i];
    if (tid < 512) sB1[tid] = b1[tid];
    if (tid < 256) sB2[tid] = b2[tid];
    for (int i = tid; i < 768; i += THREADS) sW3[i] = W3[i];

    // layer0 producer: thread owns row rp = tid>>2, k-lane kk0 = (tid&3)*8
    const int rp  = tid >> 2;
    const int kk0 = (tid & 3) * 8;
    const float cxr = coord[(row0 + rp) * 2];
    const float cyr = coord[(row0 + rp) * 2 + 1];

    __syncthreads();  // consts visible

    // produce A chunk 0 (k0 = 0) into A-buffer 0
    {
        #pragma unroll
        for (int u = 0; u < 4; ++u) {
            const int k = kk0 + 2 * u;  // k0 = 0
            float v0 = fmaxf(fmaf(cxr, sW0[k],     fmaf(cyr, sW0[1024 + k],     sB0[k])),     0.f);
            float v1 = fmaxf(fmaf(cxr, sW0[k + 1], fmaf(cyr, sW0[1024 + k + 1], sB0[k + 1])), 0.f);
            *(__half2*)(smem + SM_A1 + SWZ64((uint32_t)(rp * 64 + k * 2))) =
                __floats2half2_rn(v0, v1);
        }
    }

    // ---- per-warp tile geometry: 4 row groups x 4 col groups, 32x64 tiles ----
    const int m0  = (wid >> 2) * 32;
    const int n0w = (wid & 3) * 64;

    const int a_row = (lane & 7) + ((lane >> 3) & 1) * 8;
    const int a_kby = ((lane >> 4) & 1) * 16;
    const int b_row = (lane & 7) + ((lane >> 4) & 1) * 8;
    const int b_kby = ((lane >> 3) & 1) * 16;

    float acc[2][8][4];
    #pragma unroll
    for (int i = 0; i < 2; ++i)
        #pragma unroll
        for (int j = 0; j < 8; ++j)
            #pragma unroll
            for (int q = 0; q < 4; ++q) acc[i][j][q] = 0.f;

    // ------------------------------------------------------------------------
    // Unified pipeline step pieces
    // ------------------------------------------------------------------------
    #define STEP_HEAD(kc)                                                         \
        CP_WAIT(2);                                                               \
        __syncthreads();                                                          \
        if ((kc) + 3 < N_CHUNKS) {                                                \
            const int cn_ = (kc) + 3;                                             \
            const uint32_t dst_ = sb + SM_BR + (cn_ & 3) * 16384;                 \
            cp_async16(dst_ + SWZ64((uint32_t)(rb0 * 64 + sg * 16)),              \
                       chunk_src(cn_, rb0, sg));                                  \
            cp_async16(dst_ + SWZ64((uint32_t)((rb0 + 128) * 64 + sg * 16)),      \
                       chunk_src(cn_, rb0 + 128, sg));                            \
        }                                                                         \
        CP_COMMIT();

    #define PRODUCE_A(kc)                                                         \
        if ((kc) + 1 < 64) {                                                      \
            const int k0p = (((kc) + 1) & 31) * 32;                               \
            char* abP = smem + SM_A1 + (((kc) + 1) & 1) * 8192;                   \
            _Pragma("unroll")                                                     \
            for (int u = 0; u < 4; ++u) {                                         \
                const int kl = kk0 + 2 * u;                                       \
                const int k  = k0p + kl;                                          \
                float v0 = fmaxf(fmaf(cxr, sW0[k],     fmaf(cyr, sW0[1024 + k],     sB0[k])),     0.f); \
                float v1 = fmaxf(fmaf(cxr, sW0[k + 1], fmaf(cyr, sW0[1024 + k + 1], sB0[k + 1])), 0.f); \
                *(__half2*)(abP + SWZ64((uint32_t)(rp * 64 + kl * 2))) =          \
                    __floats2half2_rn(v0, v1);                                    \
            }                                                                     \
        }

    // MMA on chunk kc; A from 64B-row buffer (layer 1)
    #define MMA_L1(kc)                                                            \
        {                                                                         \
            const uint32_t ab = sb + SM_A1 + ((kc) & 1) * 8192;                   \
            const uint32_t bs = sb + SM_BR + ((kc) & 3) * 16384;                  \
            _Pragma("unroll")                                                     \
            for (int ks = 0; ks < 2; ++ks) {                                      \
                const int kby = ks * 32;                                          \
                uint32_t A0[4], A1f[4];                                           \
                ldsm_x4(A0[0], A0[1], A0[2], A0[3],                               \
                        ab + SWZ64((uint32_t)((m0 + a_row) * 64 + kby + a_kby))); \
                ldsm_x4(A1f[0], A1f[1], A1f[2], A1f[3],                           \
                        ab + SWZ64((uint32_t)((m0 + 16 + a_row) * 64 + kby + a_kby))); \
                _Pragma("unroll")                                                 \
                for (int j2 = 0; j2 < 4; ++j2) {                                  \
                    uint32_t bb[4];                                               \
                    ldsm_x4(bb[0], bb[1], bb[2], bb[3],                           \
                            bs + SWZ64((uint32_t)((n0w + j2 * 16 + b_row) * 64 + kby + b_kby))); \
                    mma_16816(acc[0][2 * j2],     A0[0],  A0[1],  A0[2],  A0[3],  bb[0], bb[1]); \
                    mma_16816(acc[0][2 * j2 + 1], A0[0],  A0[1],  A0[2],  A0[3],  bb[2], bb[3]); \
                    mma_16816(acc[1][2 * j2],     A1f[0], A1f[1], A1f[2], A1f[3], bb[0], bb[1]); \
                    mma_16816(acc[1][2 * j2 + 1], A1f[0], A1f[1], A1f[2], A1f[3], bb[2], bb[3]); \
                }                                                                 \
            }                                                                     \
        }

    // MMA on chunk kc; A from resident H2 (128B-row blocks, SWZ128)
    #define MMA_L2(kc)                                                            \
        {                                                                         \
            const int k0 = ((kc) - 64) * 32;                                      \
            const uint32_t ab = sb + SM_H2 + (k0 >> 6) * 16384;                   \
            const int inb = (k0 & 32) * 2;                                        \
            const uint32_t bs = sb + SM_BR + ((kc) & 3) * 16384;                  \
            _Pragma("unroll")                                                     \
            for (int ks = 0; ks < 2; ++ks) {                                      \
                const int kby = inb + ks * 32;                                    \
                uint32_t A0[4], A1f[4];                                           \
                ldsm_x4(A0[0], A0[1], A0[2], A0[3],                               \
                        ab + SWZ((uint32_t)((m0 + a_row) * 128 + kby + a_kby)));  \
                ldsm_x4(A1f[0], A1f[1], A1f[2], A1f[3],                           \
                        ab + SWZ((uint32_t)((m0 + 16 + a_row) * 128 + kby + a_kby))); \
                _Pragma("unroll")                                                 \
                for (int j2 = 0; j2 < 4; ++j2) {                                  \
                    uint32_t bb[4];                                               \
                    ldsm_x4(bb[0], bb[1], bb[2], bb[3],                           \
                            bs + SWZ64((uint32_t)((n0w + j2 * 16 + b_row) * 64 + (ks * 32) + b_kby))); \
                    mma_16816(acc[0][2 * j2],     A0[0],  A0[1],  A0[2],  A0[3],  bb[0], bb[1]); \
                    mma_16816(acc[0][2 * j2 + 1], A0[0],  A0[1],  A0[2],  A0[3],  bb[2], bb[3]); \
                    mma_16816(acc[1][2 * j2],     A1f[0], A1f[1], A1f[2], A1f[3], bb[0], bb[1]); \
                    mma_16816(acc[1][2 * j2 + 1], A1f[0], A1f[1], A1f[2], A1f[3], bb[2], bb[3]); \
                }                                                                 \
            }                                                                     \
        }

    // epilogue: h2 = relu(D1 + b1) -> H2 fp16 SWZ128 blocks, then re-zero acc
    #define EPILOGUE(pass)                                                        \
        {                                                                         \
            const int cn = (pass) * 256 + n0w;                                    \
            _Pragma("unroll")                                                     \
            for (int i = 0; i < 2; ++i) {                                         \
                const int r = m0 + i * 16 + (lane >> 2);                          \
                _Pragma("unroll")                                                 \
                for (int j = 0; j < 8; ++j) {                                     \
                    const int c = cn + j * 8 + (lane & 3) * 2;                    \
                    const float bz0 = sB1[c], bz1 = sB1[c + 1];                   \
                    float v0 = fmaxf(acc[i][j][0] + bz0, 0.f);                    \
                    float v1 = fmaxf(acc[i][j][1] + bz1, 0.f);                    \
                    float v2 = fmaxf(acc[i][j][2] + bz0, 0.f);                    \
                    float v3 = fmaxf(acc[i][j][3] + bz1, 0.f);                    \
                    const int blk = c >> 6, jj = (c & 63) * 2;                    \
                    *(__half2*)(smem + SM_H2 + blk * 16384 + SWZ((uint32_t)(r * 128 + jj))) = \
                        __floats2half2_rn(v0, v1);                                \
                    *(__half2*)(smem + SM_H2 + blk * 16384 + SWZ((uint32_t)((r + 8) * 128 + jj))) = \
                        __floats2half2_rn(v2, v3);                                \
                    acc[i][j][0] = acc[i][j][1] = acc[i][j][2] = acc[i][j][3] = 0.f; \
                }                                                                 \
            }                                                                     \
        }

    // ------------------------------------------------------------------------
    // Phase 0: layer1 pass0 (chunks 0..31)
    // ------------------------------------------------------------------------
    for (int kc = 0; kc < 32; ++kc) {
        STEP_HEAD(kc);
        PRODUCE_A(kc);
        MMA_L1(kc);
    }
    EPILOGUE(0);

    // Phase 1: layer1 pass1 (chunks 32..63)
    for (int kc = 32; kc < 64; ++kc) {
        STEP_HEAD(kc);
        PRODUCE_A(kc);
        MMA_L1(kc);
    }
    EPILOGUE(1);

    // Phase 2: layer2 (chunks 64..79), A from resident H2
    for (int kc = 64; kc < 80; ++kc) {
        STEP_HEAD(kc);
        MMA_L2(kc);
    }

    // ------------------------------------------------------------------------
    // Layer 3: out = relu(D2 + b2) @ W3 + b3
    // ------------------------------------------------------------------------
    float p[2][2][3];
    #pragma unroll
    for (int i = 0; i < 2; ++i)
        #pragma unroll
        for (int h = 0; h < 2; ++h)
            p[i][h][0] = p[i][h][1] = p[i][h][2] = 0.f;

    #pragma unroll
    for (int i = 0; i < 2; ++i) {
        #pragma unroll
        for (int j = 0; j < 8; ++j) {
            const int c = n0w + j * 8 + (lane & 3) * 2;
            #pragma unroll
            for (int q = 0; q < 4; ++q) {
                const int h  = q >> 1;
                const int cc = c + (q & 1);
                const float v = fmaxf(acc[i][j][q] + sB2[cc], 0.f);
                p[i][h][0] = fmaf(v, sW3[cc * 3 + 0], p[i][h][0]);
                p[i][h][1] = fmaf(v, sW3[cc * 3 + 1], p[i][h][1]);
                p[i][h][2] = fmaf(v, sW3[cc * 3 + 2], p[i][h][2]);
            }
        }
    }
    #pragma unroll
    for (int i = 0; i < 2; ++i)
        #pragma unroll
        for (int h = 0; h < 2; ++h)
            #pragma unroll
            for (int o = 0; o < 3; ++o) {
                float v = p[i][h][o];
                v += __shfl_xor_sync(0xffffffffu, v, 1);
                v += __shfl_xor_sync(0xffffffffu, v, 2);
                p[i][h][o] = v;
            }
    __syncthreads();  // A1 reads long done; safe to overlay sPart
    if ((lane & 3) == 0) {
        const int cg = wid & 3;
        #pragma unroll
        for (int i = 0; i < 2; ++i)
            #pragma unroll
            for (int h = 0; h < 2; ++h) {
                const int r = m0 + i * 16 + (lane >> 2) + 8 * h;
                sPart[cg * 384 + r * 3 + 0] = p[i][h][0];
                sPart[cg * 384 + r * 3 + 1] = p[i][h][1];
                sPart[cg * 384 + r * 3 + 2] = p[i][h][2];
            }
    }
    __syncthreads();

    if (tid < 384) {
        const int r = tid / 3, o = tid - r * 3;
        out[(row0 + r) * 3 + o] =
            sPart[tid] + sPart[384 + tid] + sPart[768 + tid] + sPart[1152 + tid] + b3[o];
    }
}

// ============================================================================
// Launch
// ============================================================================
extern "C" void kernel_launch(void* const* d_in, const int* in_sizes, int n_in,
                              void* d_out, int out_size) {
    const float* coord = (const float*)d_in[0];
    const float* W0    = (const float*)d_in[1];
    const float* b0    = (const float*)d_in[2];
    const float* W1    = (const float*)d_in[3];
    const float* b1    = (const float*)d_in[4];
    const float* W2    = (const float*)d_in[5];
    const float* b2    = (const float*)d_in[6];
    const float* W3    = (const float*)d_in[7];
    const float* b3    = (const float*)d_in[8];
    float* out = (float*)d_out;

    static bool attr_set = false;
    if (!attr_set) {
        cudaFuncSetAttribute(fused_mlp_kernel,
                             cudaFuncAttributeMaxDynamicSharedMemorySize, SMEM_TOTAL);
        attr_set = true;
    }

    const int prep_elems = 512 * 1024 + 256 * 512;
    prep_weights<<<(prep_elems + 255) / 256, 256>>>(W1, W2);
    fused_mlp_kernel<<<N_CTAS, THREADS, SMEM_TOTAL>>>(coord, W0, b0, b1, b2, W3, b3, out);
}